// round 1
// baseline (speedup 1.0000x reference)
#include <cuda_runtime.h>
#include <cuda_bf16.h>

// Problem constants
#define Bb 2
#define Cc 64
#define Hh 256
#define Ww 256
#define HW (Hh*Ww)
#define NUMS 63
#define LL (NUMS*NUMS)          // 3969
#define K2 64
#define EPSf 1e-5f
#define TBL_W (2*NUMS-1)        // 125

// ---------------- device scratch (no cudaMalloc allowed) ----------------
#define BCL (Bb*Cc*LL)
__device__ float g_mf [BCL];   // fg mean        [b][c][l]
__device__ float g_isf[BCL];   // 1/fg var       [b][c][l]
__device__ float g_mb [BCL];   // bg mean        [b][c][l]
__device__ float g_isb[BCL];   // 1/bg var       [b][c][l]
__device__ float g_sbv[BCL];   // bg var         [b][l][c]  (attention V)
__device__ float g_tokf[BCL];  // tok_f          [b][l][c]
__device__ float g_tokb[BCL];  // tok_b          [b][l][c]
__device__ float g_ns [BCL];   // new_std        [b][c][l]

// ---------------- Kernel 1: per-patch statistics ----------------
// grid = B*L blocks, 256 threads. thread t: channel c = t>>2, quarter j = t&3
// (rows 2j, 2j+1 of the 8x8 patch). Raw-moment formulation.
__global__ __launch_bounds__(256)
void k_stats(const float* __restrict__ x, const float* __restrict__ mask)
{
    int bl = blockIdx.x;
    int b  = bl / LL;
    int l  = bl - b * LL;
    int lh = l / NUMS, lw = l - lh * NUMS;
    int r0 = lh * 4, c0 = lw * 4;

    __shared__ float sm_m[64];
    int t = threadIdx.x;
    if (t < 64) {
        int kh = t >> 3, kw = t & 7;
        sm_m[t] = mask[(size_t)b * HW + (r0 + kh) * Ww + c0 + kw];
    }
    __syncthreads();

    int c = t >> 2;
    int j = t & 3;

    const float* xp = x + (((size_t)b * Cc + c) * Hh + r0 + 2 * j) * Ww + c0;
    float s1 = 0.f, s2 = 0.f, sm1 = 0.f, sm2 = 0.f, msum = 0.f;
    #pragma unroll
    for (int rr = 0; rr < 2; rr++) {
        float4 a = *(const float4*)(xp + rr * Ww);
        float4 bq = *(const float4*)(xp + rr * Ww + 4);
        float vv[8] = {a.x,a.y,a.z,a.w,bq.x,bq.y,bq.z,bq.w};
        #pragma unroll
        for (int kk = 0; kk < 8; kk++) {
            float m = sm_m[(2 * j + rr) * 8 + kk];
            float v = vv[kk];
            s1 += v; s2 += v * v;
            sm1 += m * v; sm2 += m * v * v;
            msum += m;
        }
    }
    // reduce over the 4 threads per channel (consecutive lanes)
    #pragma unroll
    for (int d = 1; d < 4; d <<= 1) {
        s1  += __shfl_xor_sync(0xffffffff, s1,  d);
        s2  += __shfl_xor_sync(0xffffffff, s2,  d);
        sm1 += __shfl_xor_sync(0xffffffff, sm1, d);
        sm2 += __shfl_xor_sync(0xffffffff, sm2, d);
        msum+= __shfl_xor_sync(0xffffffff, msum,d);
    }
    if (j == 0) {
        float numf = msum;
        float numb = 64.0f - msum;
        float mf = sm1 / (numf + EPSf);
        float vf = (sm2 - 2.f * mf * sm1 + mf * mf * numf) / (numf + EPSf);
        float sb1 = s1 - sm1, sb2 = s2 - sm2;
        float mb = sb1 / (numb + EPSf);
        float vb = (sb2 - 2.f * mb * sb1 + mb * mb * numb) / (numb + EPSf);
        size_t o = ((size_t)b * Cc + c) * LL + l;
        g_mf [o] = mf;
        g_isf[o] = 1.0f / vf;
        g_mb [o] = mb;
        g_isb[o] = 1.0f / vb;
        g_sbv[((size_t)b * LL + l) * Cc + c] = vb;
    }
}

// ---------------- Kernel 2: fused in_* construction + token GEMM ----------------
// tok[b,l,d] = sum_{c,k} in[b,c,l,k] * w[d,c,k]
// grid: (125 l-tiles, B, 2 types). 256 threads. TILE_L=32.
__global__ __launch_bounds__(256)
void k_gemm(const float* __restrict__ x, const float* __restrict__ mask,
            const float* __restrict__ w_fore, const float* __restrict__ w_back)
{
    int tile = blockIdx.x;
    int b    = blockIdx.y;
    int type = blockIdx.z;                 // 0 = fore, 1 = back
    const float* w    = type ? w_back : w_fore;
    const float* g_mu = type ? g_mb : g_mf;
    const float* g_is = type ? g_isb : g_isf;
    float*       g_tk = type ? g_tokb : g_tokf;

    int l0 = tile * 32;
    int t  = threadIdx.x;

    __shared__ float wsh[64][68];   // [k][d]
    __shared__ float ash[64][34];   // [k][l_local]
    __shared__ float msh[64][34];   // mm per [k][l_local]

    // --- precompute mm (type-adjusted mask) for this l-tile ---
    {
        int ll = t >> 3, kh = t & 7;
        int l = l0 + ll;
        bool valid = (l < LL);
        int lc = valid ? l : 0;
        int lh = lc / NUMS, lw = lc - lh * NUMS;
        const float* mp = mask + (size_t)b * HW + (lh * 4 + kh) * Ww + lw * 4;
        float4 a = valid ? *(const float4*)mp : make_float4(0,0,0,0);
        float4 bq = valid ? *(const float4*)(mp + 4) : make_float4(0,0,0,0);
        float mv[8] = {a.x,a.y,a.z,a.w,bq.x,bq.y,bq.z,bq.w};
        #pragma unroll
        for (int kw = 0; kw < 8; kw++) {
            float m = mv[kw];
            msh[kh * 8 + kw][ll] = type ? (1.0f - m) : m;
        }
    }

    float acc[2][4] = {{0,0,0,0},{0,0,0,0}};
    int ii = t >> 4, jj = t & 15;

    for (int c = 0; c < Cc; c++) {
        __syncthreads();
        // load w chunk transposed: wsh[k][d]
        {
            int d = t >> 2, q = t & 3;
            const float4* wp = (const float4*)(w + (size_t)d * (Cc * K2) + c * K2);
            #pragma unroll
            for (int v = 0; v < 4; v++) {
                float4 f = wp[q * 4 + v];
                int k0 = (q * 4 + v) * 4;
                wsh[k0 + 0][d] = f.x; wsh[k0 + 1][d] = f.y;
                wsh[k0 + 2][d] = f.z; wsh[k0 + 3][d] = f.w;
            }
        }
        // build A chunk: ash[k][l_local]
        {
            int ll = t >> 3, kh = t & 7;
            int l = l0 + ll;
            bool valid = (l < LL);
            int lc = valid ? l : 0;
            int lh = lc / NUMS, lw = lc - lh * NUMS;
            size_t so = ((size_t)b * Cc + c) * LL + lc;
            float mu = valid ? g_mu[so] : 0.f;
            float is = valid ? g_is[so] : 0.f;
            const float* xp = x + (((size_t)b * Cc + c) * Hh + lh * 4 + kh) * Ww + lw * 4;
            float4 a = valid ? *(const float4*)xp : make_float4(0,0,0,0);
            float4 bq = valid ? *(const float4*)(xp + 4) : make_float4(0,0,0,0);
            float xv[8] = {a.x,a.y,a.z,a.w,bq.x,bq.y,bq.z,bq.w};
            #pragma unroll
            for (int kw = 0; kw < 8; kw++) {
                int k = kh * 8 + kw;
                float mm = msh[k][ll];
                float v = (xv[kw] * mm - mu) * is * mm + mu * (1.0f - mm);
                ash[k][ll] = v;
            }
        }
        __syncthreads();
        // accumulate 2(l) x 4(d) per thread over k
        #pragma unroll 8
        for (int k = 0; k < 64; k++) {
            float2 av = *(const float2*)&ash[k][2 * ii];
            float4 wv = *(const float4*)&wsh[k][4 * jj];
            acc[0][0] += av.x * wv.x; acc[0][1] += av.x * wv.y;
            acc[0][2] += av.x * wv.z; acc[0][3] += av.x * wv.w;
            acc[1][0] += av.y * wv.x; acc[1][1] += av.y * wv.y;
            acc[1][2] += av.y * wv.z; acc[1][3] += av.y * wv.w;
        }
    }
    // write tok [b][l][d]
    #pragma unroll
    for (int li = 0; li < 2; li++) {
        int l = l0 + 2 * ii + li;
        if (l < LL) {
            float4 o = make_float4(acc[li][0], acc[li][1], acc[li][2], acc[li][3]);
            *(float4*)(g_tk + ((size_t)b * LL + l) * Cc + 4 * jj) = o;
        }
    }
}

// ---------------- Kernel 3: attention (flash-style, online softmax) ----------------
// logits[l,m] = <tok_f[l], tok_b[m]> + rpb[rel(l,m)] ; S = softmax_m
// new_std[b,c,l] = sum_m S[l,m] * sbv[b,m,c]
// grid: (ceil(L/64), B). 256 threads: row_local = t>>2 (64 rows), cg = t&3 (16 ch)
__global__ __launch_bounds__(256)
void k_attn(const float* __restrict__ rpb)
{
    int b  = blockIdx.y;
    int l0 = blockIdx.x * 64;
    int t  = threadIdx.x;
    int rloc = t >> 2;
    int cg   = t & 3;
    int cbase = cg * 16;

    int l = l0 + rloc;
    bool rvalid = (l < LL);
    int lr = rvalid ? l : (LL - 1);
    int lh = lr / NUMS, lw = lr - lh * NUMS;

    __shared__ float kb[64][64];
    __shared__ float vv[64][64];
    __shared__ int   mhs[64];
    __shared__ int   mws[64];

    float q[16];
    {
        const float4* qp = (const float4*)(g_tokf + ((size_t)b * LL + lr) * Cc + cbase);
        #pragma unroll
        for (int u = 0; u < 4; u++) {
            float4 f = qp[u];
            q[4*u+0]=f.x; q[4*u+1]=f.y; q[4*u+2]=f.z; q[4*u+3]=f.w;
        }
    }
    float acc[16];
    #pragma unroll
    for (int i = 0; i < 16; i++) acc[i] = 0.f;
    float mrun = -1e30f, drun = 0.f;

    const int NT = (LL + 63) / 64;   // 63 tiles
    for (int ti = 0; ti < NT; ti++) {
        int m0 = ti * 64;
        int cnt = min(64, LL - m0);
        __syncthreads();
        // load K tile + V tile (flat float4 copies)
        for (int i = t; i < 1024; i += 256) {
            int row = i >> 4;
            int m = m0 + row;
            float4 z = make_float4(0,0,0,0);
            ((float4*)kb)[i] = (m < LL) ? ((const float4*)(g_tokb + ((size_t)b*LL + m)*Cc))[i & 15] : z;
            ((float4*)vv)[i] = (m < LL) ? ((const float4*)(g_sbv  + ((size_t)b*LL + m)*Cc))[i & 15] : z;
        }
        if (t < 64) {
            int m = m0 + t;
            int mh = m / NUMS;
            mhs[t] = mh; mws[t] = m - mh * NUMS;
        }
        __syncthreads();

        // pass 1: logits, keep my 16 (j%4==cg) in regs, track tile max
        float lreg[16];
        float tmax = -1e30f;
        #pragma unroll 4
        for (int jg = 0; jg < 16; jg++) {
            #pragma unroll
            for (int qq = 0; qq < 4; qq++) {
                int jidx = jg * 4 + qq;
                float s;
                if (jidx < cnt) {
                    float partial = 0.f;
                    #pragma unroll
                    for (int u = 0; u < 4; u++) {
                        float4 kv = *(const float4*)&kb[jidx][cbase + 4*u];
                        partial += q[4*u+0]*kv.x + q[4*u+1]*kv.y
                                 + q[4*u+2]*kv.z + q[4*u+3]*kv.w;
                    }
                    if (cg == 0) {
                        int bi = (lh - mhs[jidx] + (NUMS-1)) * TBL_W + (lw - mws[jidx] + (NUMS-1));
                        partial += __ldg(rpb + bi);
                    }
                    partial += __shfl_xor_sync(0xffffffff, partial, 1);
                    partial += __shfl_xor_sync(0xffffffff, partial, 2);
                    s = partial;
                } else {
                    s = -1e30f;
                }
                tmax = fmaxf(tmax, s);
                if (qq == cg) lreg[jg] = s;
            }
        }
        // pass 2: online softmax update
        float nm = fmaxf(mrun, tmax);
        float scale = __expf(mrun - nm);
        drun *= scale;
        #pragma unroll
        for (int i = 0; i < 16; i++) acc[i] *= scale;
        #pragma unroll 4
        for (int jg = 0; jg < 16; jg++) {
            float pj = __expf(lreg[jg] - nm);
            drun += pj;
            #pragma unroll
            for (int qq = 0; qq < 4; qq++) {
                float p = __shfl_sync(0xffffffff, pj, qq, 4);
                int jidx = jg * 4 + qq;
                #pragma unroll
                for (int u = 0; u < 4; u++) {
                    float4 vf = *(const float4*)&vv[jidx][cbase + 4*u];
                    acc[4*u+0] += p * vf.x; acc[4*u+1] += p * vf.y;
                    acc[4*u+2] += p * vf.z; acc[4*u+3] += p * vf.w;
                }
            }
        }
        mrun = nm;
    }
    // total denom across the quad (each thread summed its own j's)
    drun += __shfl_xor_sync(0xffffffff, drun, 1);
    drun += __shfl_xor_sync(0xffffffff, drun, 2);
    float inv = 1.0f / drun;
    if (rvalid) {
        #pragma unroll
        for (int i = 0; i < 16; i++) {
            g_ns[((size_t)b * Cc + cbase + i) * LL + l] = acc[i] * inv;
        }
    }
}

// ---------------- Kernel 4: fold + epilogue ----------------
// out = fold(in_f*ns + ns)/count * (1+fg_g) + fg_b, *mask, + unorm_bg
__global__ __launch_bounds__(256)
void k_epilogue(const float* __restrict__ x, const float* __restrict__ mask,
                const float* __restrict__ fg_g, const float* __restrict__ fg_b,
                const float* __restrict__ bg_g, const float* __restrict__ bg_b,
                float* __restrict__ out)
{
    int idx = blockIdx.x * 256 + threadIdx.x;
    // idx -> b,c,h,w
    int w = idx & 255;
    int h = (idx >> 8) & 255;
    int c = (idx >> 16) & 63;
    int b = idx >> 22;

    float m   = mask[(size_t)b * HW + h * Ww + w];
    float inm = 1.0f - m;
    float xv  = x[idx];
    float bgv = xv * inm;
    float ubg = (bgv * (1.0f + bg_g[c]) + bg_b[c]) * inm;
    float xm  = xv * m;

    // covering patch rows/cols (at most 2 each)
    int ihs[2]; int nh = 0;
    int kh0 = h & 3;
    {
        int d = h - kh0;       { int ih = d >> 2; if (ih <= NUMS-1) ihs[nh++] = ih; }
        int d2 = h - (kh0 + 4); if (d2 >= 0) { int ih = d2 >> 2; if (ih <= NUMS-1) ihs[nh++] = ih; }
    }
    int iws[2]; int nw = 0;
    int kw0 = w & 3;
    {
        int d = w - kw0;       { int iw = d >> 2; if (iw <= NUMS-1) iws[nw++] = iw; }
        int d2 = w - (kw0 + 4); if (d2 >= 0) { int iw = d2 >> 2; if (iw <= NUMS-1) iws[nw++] = iw; }
    }

    float sum = 0.f;
    int count = 0;
    size_t base = ((size_t)b * Cc + c) * LL;
    for (int a = 0; a < nh; a++) {
        for (int e = 0; e < nw; e++) {
            int l = ihs[a] * NUMS + iws[e];
            float mu = g_mf [base + l];
            float is = g_isf[base + l];
            float ns = g_ns [base + l];
            float inf_ = (xm - mu) * is * m + mu * inm;
            sum += inf_ * ns + ns;
            count++;
        }
    }
    float val = (sum / (float)count) * (1.0f + fg_g[c]) + fg_b[c];
    val = val * m + ubg;
    out[idx] = val;
}

// ---------------- launch ----------------
extern "C" void kernel_launch(void* const* d_in, const int* in_sizes, int n_in,
                              void* d_out, int out_size)
{
    const float* x       = (const float*)d_in[0];
    const float* mask    = (const float*)d_in[1];
    const float* fg_g    = (const float*)d_in[2];
    const float* fg_b    = (const float*)d_in[3];
    const float* bg_g    = (const float*)d_in[4];
    const float* bg_b    = (const float*)d_in[5];
    const float* w_fore  = (const float*)d_in[6];
    const float* w_back  = (const float*)d_in[7];
    const float* rpb     = (const float*)d_in[8];
    float* out = (float*)d_out;

    k_stats<<<Bb * LL, 256>>>(x, mask);
    k_gemm<<<dim3((LL + 31) / 32, Bb, 2), 256>>>(x, mask, w_fore, w_back);
    k_attn<<<dim3((LL + 63) / 64, Bb), 256>>>(rpb);
    k_epilogue<<<(Bb * Cc * HW) / 256, 256>>>(x, mask, fg_g, fg_b, bg_g, bg_b, out);
}

// round 4
// speedup vs baseline: 1.2393x; 1.2393x over previous
#include <cuda_runtime.h>
#include <cuda_bf16.h>

#define Bb 2
#define Cc 64
#define Hh 256
#define Ww 256
#define HW (Hh*Ww)
#define NUMS 63
#define LL (NUMS*NUMS)          // 3969
#define EPSf 1e-5f
#define TBL_W (2*NUMS-1)        // 125

// ---------------- device scratch ----------------
#define BCL (Bb*Cc*LL)
__device__ float2 g_mif[BCL];   // (fg mean, 1/fg var)   [b][c][l]
__device__ float2 g_mib[BCL];   // (bg mean, 1/bg var)   [b][c][l]
__device__ float  g_sbv[BCL];   // bg var                 [b][l][c]
__device__ float  g_tokf[BCL];  // tok_f                  [b][l][c]
__device__ float  g_tokb[BCL];  // tok_b                  [b][l][c]
__device__ float  g_ns [BCL];   // new_std                [b][c][l]

// ---------------- Kernel 1: per-patch statistics ----------------
__global__ __launch_bounds__(256)
void k_stats(const float* __restrict__ x, const float* __restrict__ mask)
{
    int bl = blockIdx.x;
    int b  = bl / LL;
    int l  = bl - b * LL;
    int lh = l / NUMS, lw = l - lh * NUMS;
    int r0 = lh * 4, c0 = lw * 4;

    __shared__ float sm_m[64];
    int t = threadIdx.x;
    if (t < 64) {
        int kh = t >> 3, kw = t & 7;
        sm_m[t] = mask[(size_t)b * HW + (r0 + kh) * Ww + c0 + kw];
    }
    __syncthreads();

    int c = t >> 2;
    int j = t & 3;

    const float* xp = x + (((size_t)b * Cc + c) * Hh + r0 + 2 * j) * Ww + c0;
    float s1 = 0.f, s2 = 0.f, sm1 = 0.f, sm2 = 0.f, msum = 0.f;
    #pragma unroll
    for (int rr = 0; rr < 2; rr++) {
        float4 a = *(const float4*)(xp + rr * Ww);
        float4 bq = *(const float4*)(xp + rr * Ww + 4);
        float vv[8] = {a.x,a.y,a.z,a.w,bq.x,bq.y,bq.z,bq.w};
        #pragma unroll
        for (int kk = 0; kk < 8; kk++) {
            float m = sm_m[(2 * j + rr) * 8 + kk];
            float v = vv[kk];
            s1 += v; s2 += v * v;
            sm1 += m * v; sm2 += m * v * v;
            msum += m;
        }
    }
    #pragma unroll
    for (int d = 1; d < 4; d <<= 1) {
        s1  += __shfl_xor_sync(0xffffffff, s1,  d);
        s2  += __shfl_xor_sync(0xffffffff, s2,  d);
        sm1 += __shfl_xor_sync(0xffffffff, sm1, d);
        sm2 += __shfl_xor_sync(0xffffffff, sm2, d);
        msum+= __shfl_xor_sync(0xffffffff, msum,d);
    }
    if (j == 0) {
        float numf = msum;
        float numb = 64.0f - msum;
        float mf = sm1 / (numf + EPSf);
        float vf = (sm2 - 2.f * mf * sm1 + mf * mf * numf) / (numf + EPSf);
        float sb1 = s1 - sm1, sb2 = s2 - sm2;
        float mb = sb1 / (numb + EPSf);
        float vb = (sb2 - 2.f * mb * sb1 + mb * mb * numb) / (numb + EPSf);
        size_t o = ((size_t)b * Cc + c) * LL + l;
        g_mif[o] = make_float2(mf, 1.0f / vf);
        g_mib[o] = make_float2(mb, 1.0f / vb);
        g_sbv[((size_t)b * LL + l) * Cc + c] = vb;
    }
}

// ---------------- Kernel 2: fused in_* build + token GEMM ----------------
// Block tile: 128 L x 64 D, K = 64c x 64k staged 32-k at a time, prefetched.
// 256 threads: compute map lgrp=t>>4 (8 L each), dgrp=t&15 (4 D each) -> 32 acc.
__global__ __launch_bounds__(256)
void k_gemm(const float* __restrict__ x, const float* __restrict__ mask,
            const float* __restrict__ w_fore, const float* __restrict__ w_back)
{
    int tile = blockIdx.x;               // 0..31
    int b    = blockIdx.y;
    int type = blockIdx.z;               // 0 = fore, 1 = back
    const float*  w    = type ? w_back : w_fore;
    const float2* g_mi = type ? g_mib : g_mif;
    float*        g_tk = type ? g_tokb : g_tokf;

    int l0 = tile * 128;
    int t  = threadIdx.x;

    __shared__ float ash[32][128];
    __shared__ float wsh[32][68];
    __shared__ unsigned int smb[128][2];   // mask bits per l (type-adjusted)

    // A-side thread mapping
    int la    = t & 127;
    int halfa = t >> 7;                  // 0/1 -> 2 rows each within a 4-row phase
    int lgl   = l0 + la;
    bool lvalid = lgl < LL;
    int lg = lvalid ? lgl : (LL - 1);
    int lh = lg / NUMS, lw = lg - lh * NUMS;

    // build mask bit words (word s covers patch rows 4s..4s+3)
    if (halfa == 0) {
        unsigned int w0 = 0, w1 = 0;
        const float* mp = mask + (size_t)b * HW + (lh * 4) * Ww + lw * 4;
        #pragma unroll
        for (int r = 0; r < 8; r++) {
            float4 a = *(const float4*)(mp + r * Ww);
            float4 bq = *(const float4*)(mp + r * Ww + 4);
            float mv[8] = {a.x,a.y,a.z,a.w,bq.x,bq.y,bq.z,bq.w};
            unsigned int bits = 0;
            #pragma unroll
            for (int kw = 0; kw < 8; kw++) {
                bool on = mv[kw] > 0.5f;
                if (type) on = !on;
                bits |= (on ? 1u : 0u) << (((r & 3) * 8) + kw);
            }
            if (r < 4) w0 |= bits; else w1 |= bits;
        }
        smb[la][0] = w0; smb[la][1] = w1;
    }

    // W-side thread mapping (conflict-free STS, k-major)
    int wd = t & 63;          // output channel d
    int wi = t >> 6;          // k-subgroup 0..3 (8 k each)

    int lgrp = t >> 4, dgrp = t & 15;

    float acc[8][4];
    #pragma unroll
    for (int i = 0; i < 8; i++)
        #pragma unroll
        for (int j2 = 0; j2 < 4; j2++) acc[i][j2] = 0.f;

    // prefetch registers
    float4 xr0, xr1, xr2, xr3, wr0, wr1;
    float2 mi;

    auto LD = [&](int p) {
        int c = p >> 1, sub = p & 1;
        const float* xp = x + (((size_t)b * Cc + c) * Hh + lh * 4 + sub * 4 + halfa * 2) * Ww + lw * 4;
        xr0 = *(const float4*)xp;
        xr1 = *(const float4*)(xp + 4);
        xr2 = *(const float4*)(xp + Ww);
        xr3 = *(const float4*)(xp + Ww + 4);
        mi  = g_mi[((size_t)b * Cc + c) * LL + lg];
        const float* wp = w + (size_t)wd * (Cc * 64) + c * 64 + sub * 32 + wi * 8;
        wr0 = *(const float4*)wp;
        wr1 = *(const float4*)(wp + 4);
    };
    LD(0);

    for (int p = 0; p < 128; p++) {
        __syncthreads();
        // ---- stage A (rows halfa*2, halfa*2+1 of this 4-row phase) ----
        {
            int sub = p & 1;
            float muv = lvalid ? mi.x : 0.f;
            float isv = lvalid ? mi.y : 0.f;
            unsigned int wsel = smb[la][sub];
            float xv[16] = {xr0.x,xr0.y,xr0.z,xr0.w, xr1.x,xr1.y,xr1.z,xr1.w,
                            xr2.x,xr2.y,xr2.z,xr2.w, xr3.x,xr3.y,xr3.z,xr3.w};
            #pragma unroll
            for (int rr = 0; rr < 2; rr++) {
                int row = halfa * 2 + rr;
                #pragma unroll
                for (int kw = 0; kw < 8; kw++) {
                    bool on = (wsel >> (row * 8 + kw)) & 1u;
                    float v = on ? (xv[rr * 8 + kw] - muv) * isv : muv;
                    ash[row * 8 + kw][la] = v;
                }
            }
        }
        // ---- stage W ----
        {
            float wv[8] = {wr0.x,wr0.y,wr0.z,wr0.w, wr1.x,wr1.y,wr1.z,wr1.w};
            #pragma unroll
            for (int q = 0; q < 8; q++) wsh[wi * 8 + q][wd] = wv[q];
        }
        __syncthreads();
        if (p < 127) LD(p + 1);

        // ---- compute 32 k slices: 8L x 4D scalar FFMA ----
        #pragma unroll 4
        for (int k = 0; k < 32; k++) {
            float4 a0 = *(const float4*)&ash[k][8 * lgrp];
            float4 a1 = *(const float4*)&ash[k][8 * lgrp + 4];
            float4 wv = *(const float4*)&wsh[k][4 * dgrp];
            float av[8] = {a0.x,a0.y,a0.z,a0.w, a1.x,a1.y,a1.z,a1.w};
            #pragma unroll
            for (int li = 0; li < 8; li++) {
                acc[li][0] += av[li] * wv.x;
                acc[li][1] += av[li] * wv.y;
                acc[li][2] += av[li] * wv.z;
                acc[li][3] += av[li] * wv.w;
            }
        }
    }

    // ---- write tok [b][l][d] ----
    #pragma unroll
    for (int li = 0; li < 8; li++) {
        int l = l0 + 8 * lgrp + li;
        if (l < LL) {
            float4 o = make_float4(acc[li][0], acc[li][1], acc[li][2], acc[li][3]);
            *(float4*)(g_tk + ((size_t)b * LL + l) * Cc + 4 * dgrp) = o;
        }
    }
}

// ---------------- Kernel 3: attention (flash-style, tree-reduced logits) ----------------
// 64 rows/block, quad (4 threads) per row, 16 ch each.
__global__ __launch_bounds__(256)
void k_attn(const float* __restrict__ rpb)
{
    int b  = blockIdx.y;
    int l0 = blockIdx.x * 64;
    int t  = threadIdx.x;
    int rloc = t >> 2;
    int cg   = t & 3;
    int cbase = cg * 16;

    int l = l0 + rloc;
    bool rvalid = (l < LL);
    int lr = rvalid ? l : (LL - 1);
    int lh = lr / NUMS, lw = lr - lh * NUMS;

    __shared__ float kb[64][64];
    __shared__ float vv[64][64];
    __shared__ int   mhs[64];
    __shared__ int   mws[64];

    float q[16];
    {
        const float4* qp = (const float4*)(g_tokf + ((size_t)b * LL + lr) * Cc + cbase);
        #pragma unroll
        for (int u = 0; u < 4; u++) {
            float4 f = qp[u];
            q[4*u+0]=f.x; q[4*u+1]=f.y; q[4*u+2]=f.z; q[4*u+3]=f.w;
        }
    }
    float acc[16];
    #pragma unroll
    for (int i = 0; i < 16; i++) acc[i] = 0.f;
    float mrun = -1e30f, drun = 0.f;

    const int NT = (LL + 63) / 64;   // 63 tiles
    for (int ti = 0; ti < NT; ti++) {
        int m0 = ti * 64;
        int cnt = min(64, LL - m0);
        __syncthreads();
        for (int i = t; i < 1024; i += 256) {
            int row = i >> 4;
            int m = m0 + row;
            float4 z = make_float4(0,0,0,0);
            ((float4*)kb)[i] = (m < LL) ? ((const float4*)(g_tokb + ((size_t)b*LL + m)*Cc))[i & 15] : z;
            ((float4*)vv)[i] = (m < LL) ? ((const float4*)(g_sbv  + ((size_t)b*LL + m)*Cc))[i & 15] : z;
        }
        if (t < 64) {
            int m = min(m0 + t, LL - 1);
            int mh = m / NUMS;
            mhs[t] = mh; mws[t] = m - mh * NUMS;
        }
        __syncthreads();

        // ---- pass 1: logits. Each thread computes 16-ch partials for 4 j's,
        // then a 2-step quad tree-exchange yields full 64-ch dot for j = jg*4+cg.
        float lreg[16];
        float tmax = -1e30f;
        #pragma unroll 2
        for (int jg = 0; jg < 16; jg++) {
            float p[4];
            #pragma unroll
            for (int jq = 0; jq < 4; jq++) {
                int jidx = jg * 4 + jq;
                float s = 0.f;
                #pragma unroll
                for (int u = 0; u < 4; u++) {
                    float4 kv = *(const float4*)&kb[jidx][cbase + 4*u];
                    s += q[4*u+0]*kv.x + q[4*u+1]*kv.y
                       + q[4*u+2]*kv.z + q[4*u+3]*kv.w;
                }
                p[jq] = s;
            }
            // step 1 (xor 1): keep j with (j&1)==(cg&1)
            bool lo1 = (cg & 1) == 0;
            float s0 = lo1 ? p[1] : p[0];
            float s1 = lo1 ? p[3] : p[2];
            s0 = __shfl_xor_sync(0xffffffff, s0, 1);
            s1 = __shfl_xor_sync(0xffffffff, s1, 1);
            float q0 = (lo1 ? p[0] : p[1]) + s0;   // j = (cg&1)
            float q1 = (lo1 ? p[2] : p[3]) + s1;   // j = 2 + (cg&1)
            // step 2 (xor 2): keep j with (j&2)==(cg&2)
            bool lo2 = (cg & 2) == 0;
            float s2 = lo2 ? q1 : q0;
            s2 = __shfl_xor_sync(0xffffffff, s2, 2);
            float tot = (lo2 ? q0 : q1) + s2;      // full dot for j = jg*4+cg
            int jown = jg * 4 + cg;
            if (jown < cnt) {
                int bi = (lh - mhs[jown] + (NUMS-1)) * TBL_W + (lw - mws[jown] + (NUMS-1));
                tot += __ldg(rpb + bi);
            } else {
                tot = -1e30f;
            }
            lreg[jg] = tot;
            tmax = fmaxf(tmax, tot);
        }
        // quad-consistent tile max
        tmax = fmaxf(tmax, __shfl_xor_sync(0xffffffff, tmax, 1));
        tmax = fmaxf(tmax, __shfl_xor_sync(0xffffffff, tmax, 2));

        // ---- pass 2: online softmax + PV ----
        float nm = fmaxf(mrun, tmax);
        float scale = __expf(mrun - nm);
        drun *= scale;
        #pragma unroll
        for (int i = 0; i < 16; i++) acc[i] *= scale;
        #pragma unroll 4
        for (int jg = 0; jg < 16; jg++) {
            float pj = __expf(lreg[jg] - nm);
            drun += pj;
            #pragma unroll
            for (int qq = 0; qq < 4; qq++) {
                float p = __shfl_sync(0xffffffff, pj, qq, 4);
                int jidx = jg * 4 + qq;
                #pragma unroll
                for (int u = 0; u < 4; u++) {
                    float4 vf = *(const float4*)&vv[jidx][cbase + 4*u];
                    acc[4*u+0] += p * vf.x; acc[4*u+1] += p * vf.y;
                    acc[4*u+2] += p * vf.z; acc[4*u+3] += p * vf.w;
                }
            }
        }
        mrun = nm;
    }
    drun += __shfl_xor_sync(0xffffffff, drun, 1);
    drun += __shfl_xor_sync(0xffffffff, drun, 2);
    float inv = 1.0f / drun;
    if (rvalid) {
        #pragma unroll
        for (int i = 0; i < 16; i++) {
            g_ns[((size_t)b * Cc + cbase + i) * LL + l] = acc[i] * inv;
        }
    }
}

// ---------------- Kernel 4: fold + epilogue ----------------
__global__ __launch_bounds__(256)
void k_epilogue(const float* __restrict__ x, const float* __restrict__ mask,
                const float* __restrict__ fg_g, const float* __restrict__ fg_b,
                const float* __restrict__ bg_g, const float* __restrict__ bg_b,
                float* __restrict__ out)
{
    int idx = blockIdx.x * 256 + threadIdx.x;
    int w = idx & 255;
    int h = (idx >> 8) & 255;
    int c = (idx >> 16) & 63;
    int b = idx >> 22;

    float m   = mask[(size_t)b * HW + h * Ww + w];
    float inm = 1.0f - m;
    float xv  = x[idx];
    float ubg = (xv * inm * (1.0f + bg_g[c]) + bg_b[c]) * inm;
    float xm  = xv * m;

    int ihs[2]; int nh = 0;
    int kh0 = h & 3;
    {
        int d = h - kh0;        { int ih = d >> 2; if (ih <= NUMS-1) ihs[nh++] = ih; }
        int d2 = h - (kh0 + 4); if (d2 >= 0) { int ih = d2 >> 2; if (ih <= NUMS-1) ihs[nh++] = ih; }
    }
    int iws[2]; int nw = 0;
    int kw0 = w & 3;
    {
        int d = w - kw0;        { int iw = d >> 2; if (iw <= NUMS-1) iws[nw++] = iw; }
        int d2 = w - (kw0 + 4); if (d2 >= 0) { int iw = d2 >> 2; if (iw <= NUMS-1) iws[nw++] = iw; }
    }

    float sum = 0.f;
    size_t base = ((size_t)b * Cc + c) * LL;
    for (int a = 0; a < nh; a++) {
        for (int e = 0; e < nw; e++) {
            int lp = ihs[a] * NUMS + iws[e];
            float2 mi = g_mif[base + lp];
            float ns  = g_ns [base + lp];
            float inf_ = (xm - mi.x) * mi.y * m + mi.x * inm;
            sum += inf_ * ns + ns;
        }
    }
    int count = nh * nw;                    // 1, 2 or 4
    float invc = (count == 4) ? 0.25f : ((count == 2) ? 0.5f : 1.0f);
    float val = (sum * invc) * (1.0f + fg_g[c]) + fg_b[c];
    val = val * m + ubg;
    out[idx] = val;
}

// ---------------- launch ----------------
extern "C" void kernel_launch(void* const* d_in, const int* in_sizes, int n_in,
                              void* d_out, int out_size)
{
    const float* x       = (const float*)d_in[0];
    const float* mask    = (const float*)d_in[1];
    const float* fg_g    = (const float*)d_in[2];
    const float* fg_b    = (const float*)d_in[3];
    const float* bg_g    = (const float*)d_in[4];
    const float* bg_b    = (const float*)d_in[5];
    const float* w_fore  = (const float*)d_in[6];
    const float* w_back  = (const float*)d_in[7];
    const float* rpb     = (const float*)d_in[8];
    float* out = (float*)d_out;

    k_stats<<<Bb * LL, 256>>>(x, mask);
    k_gemm<<<dim3((LL + 127) / 128, Bb, 2), 256>>>(x, mask, w_fore, w_back);
    k_attn<<<dim3((LL + 63) / 64, Bb), 256>>>(rpb);
    k_epilogue<<<(Bb * Cc * HW) / 256, 256>>>(x, mask, fg_g, fg_b, bg_g, bg_b, out);
}